// round 17
// baseline (speedup 1.0000x reference)
#include <cuda_runtime.h>
#include <math.h>

#define NB 256
#define NS 512
#define ND 128
#define NH 256
#define NHH 128
#define NL 64

#define NG   16   // batch groups (clusters)
#define BPG  16   // batches per group
#define CLU  8    // CTAs per cluster

typedef unsigned long long u64;

// ---------------- device-global scratch ----------------
__device__ float  g_emb[(size_t)NB * NS * ND];            // emb[b][s][d]
__device__ float  g_h2seq[(size_t)NS * NG * NH * BPG];    // [t][g][k][b] (float2-pair layout for l2loss)
__device__ float  g_h1x[2 * NG * NH * BPG];               // kpair-interleaved [par][g][kp][b-pairs]
__device__ float  g_h2x[2 * NG * NHH * BPG];
__device__ float  g_hd1x[2 * NG * NHH * BPG];
__device__ float  g_hd2x[2 * NG * NH * BPG];
__device__ float  g_lat[NB * NL];
__device__ float  g_gi1[NB * 3 * NHH];
__device__ double g_losspart[1024];

static __device__ __forceinline__ float sigf(float v) { return 1.0f / (1.0f + expf(-v)); }

static __device__ __forceinline__ void fma2(u64& a, u64 b, u64 c) {
    asm("fma.rn.f32x2 %0, %1, %2, %0;" : "+l"(a) : "l"(b), "l"(c));
}
static __device__ __forceinline__ float hsum2(u64 v) {
    float lo, hi;
    asm("mov.b64 {%0,%1}, %2;" : "=f"(lo), "=f"(hi) : "l"(v));
    return lo + hi;
}
static __device__ __forceinline__ u64 pack2(float lo, float hi) {
    u64 r;
    asm("mov.b64 %0, {%1,%2};" : "=l"(r) : "f"(lo), "f"(hi));
    return r;
}
static __device__ __forceinline__ void cbar() {
    // arrive has .release / wait has .acquire semantics by default (PTX) —
    // orders the preceding STG exchange stores for peer __ldcg reads.
    asm volatile("barrier.cluster.arrive.aligned;" ::: "memory");
    asm volatile("barrier.cluster.wait.aligned;"   ::: "memory");
}

// float index of logical (k, b) in kpair-interleaved layout
#define KP(k, b) ((((k) >> 1) * (2 * BPG)) + ((b) * 2) + ((k) & 1))

// one 4-k chunk of 3-gate x 2-batch accumulation (f32x2 along k)
#define GSTEP(Wr, Wz, Wn, HQ, kc, aR0, aR1, aZ0, aZ1, aN0, aN1) do {              \
    ulonglong2 _wr = *(const ulonglong2*)((Wr) + (kc));                            \
    ulonglong2 _wz = *(const ulonglong2*)((Wz) + (kc));                            \
    ulonglong2 _wn = *(const ulonglong2*)((Wn) + (kc));                            \
    ulonglong2 _hA = *(const ulonglong2*)((HQ) + (2 * (kc)) * BPG + 2 * bp);       \
    ulonglong2 _hB = *(const ulonglong2*)((HQ) + (2 * (kc) + 1) * BPG + 2 * bp);   \
    fma2(aR0, _wr.x, _hA.x); fma2(aR1, _wr.x, _hA.y);                              \
    fma2(aR0, _wr.y, _hB.x); fma2(aR1, _wr.y, _hB.y);                              \
    fma2(aZ0, _wz.x, _hA.x); fma2(aZ1, _wz.x, _hA.y);                              \
    fma2(aZ0, _wz.y, _hB.x); fma2(aZ1, _wz.y, _hB.y);                              \
    fma2(aN0, _wn.x, _hA.x); fma2(aN1, _wn.x, _hA.y);                              \
    fma2(aN0, _wn.y, _hB.x); fma2(aN1, _wn.y, _hB.y);                              \
} while (0)

// ---------------- init ----------------
__global__ void init_kernel() {
    int i = blockIdx.x * blockDim.x + threadIdx.x;
    if (i < 1024) g_losspart[i] = 0.0;
}

// ---------------- embedding ----------------
__global__ __launch_bounds__(256) void emb_kernel(const int* __restrict__ tok,
                                                  const float* __restrict__ pw,
                                                  const float* __restrict__ sw) {
    const int n4 = NB * NS * ND / 4;
    const float4* p4 = (const float4*)pw;
    const float4* s4 = (const float4*)sw;
    float4* e4 = (float4*)g_emb;
    for (int i = blockIdx.x * blockDim.x + threadIdx.x; i < n4; i += gridDim.x * blockDim.x) {
        int bs = i >> 5;
        int c = i & 31;
        int p = tok[(size_t)bs * 2 + 0];
        int q = tok[(size_t)bs * 2 + 1];
        float4 a = p4[(size_t)p * 32 + c];
        float4 b = s4[(size_t)q * 32 + c];
        e4[i] = make_float4(a.x + b.x, a.y + b.y, a.z + b.z, a.w + b.w);
    }
}

// ======================= ENCODER (1 cluster barrier per step) =======================
__global__ __launch_bounds__(256, 1) __cluster_dims__(CLU, 1, 1)
void enc_kernel(const float* __restrict__ e1_Wih, const float* __restrict__ e1_Whh,
                const float* __restrict__ e1_bih, const float* __restrict__ e1_bhh,
                const float* __restrict__ e2_Wih, const float* __restrict__ e2_Whh,
                const float* __restrict__ e2_bih, const float* __restrict__ e2_bhh) {
    __shared__ float sh_h1[NH * BPG];       // 16 KB, kpair-interleaved
    __shared__ float sh_h2[NHH * BPG];      // 8 KB
    __shared__ float sh_x[2][ND * BPG];     // 16 KB, double-buffered

    const int tid = threadIdx.x;
    const int rank = blockIdx.x & (CLU - 1);
    const int g = blockIdx.x >> 3;
    const int bp = tid & 7;

    // enc1 mapping: 32 j per CTA
    const int j1 = rank * 32 + (tid >> 3);
    const float b1r  = e1_bih[j1] + e1_bhh[j1];
    const float b1z  = e1_bih[NH + j1] + e1_bhh[NH + j1];
    const float b1in = e1_bih[2 * NH + j1];
    const float b1hn = e1_bhh[2 * NH + j1];
    const ulonglong2* w1r_h = (const ulonglong2*)(e1_Whh + (size_t)j1 * NH);
    const ulonglong2* w1z_h = (const ulonglong2*)(e1_Whh + (size_t)(NH + j1) * NH);
    const ulonglong2* w1n_h = (const ulonglong2*)(e1_Whh + (size_t)(2 * NH + j1) * NH);
    const ulonglong2* w1r_x = (const ulonglong2*)(e1_Wih + (size_t)j1 * ND);
    const ulonglong2* w1z_x = (const ulonglong2*)(e1_Wih + (size_t)(NH + j1) * ND);
    const ulonglong2* w1n_x = (const ulonglong2*)(e1_Wih + (size_t)(2 * NH + j1) * ND);

    // enc2 mapping: 16 j per CTA (tid < 128)
    const int j2 = rank * 16 + (tid >> 3);
    float b2r = 0.f, b2z = 0.f, b2in = 0.f, b2hn = 0.f;
    const ulonglong2 *w2r_h = 0, *w2z_h = 0, *w2n_h = 0, *w2r_x = 0, *w2z_x = 0, *w2n_x = 0;
    if (tid < 128) {
        b2r  = e2_bih[j2] + e2_bhh[j2];
        b2z  = e2_bih[NHH + j2] + e2_bhh[NHH + j2];
        b2in = e2_bih[2 * NHH + j2];
        b2hn = e2_bhh[2 * NHH + j2];
        w2r_h = (const ulonglong2*)(e2_Whh + (size_t)j2 * NHH);
        w2z_h = (const ulonglong2*)(e2_Whh + (size_t)(NHH + j2) * NHH);
        w2n_h = (const ulonglong2*)(e2_Whh + (size_t)(2 * NHH + j2) * NHH);
        w2r_x = (const ulonglong2*)(e2_Wih + (size_t)j2 * NH);
        w2z_x = (const ulonglong2*)(e2_Wih + (size_t)(NHH + j2) * NH);
        w2n_x = (const ulonglong2*)(e2_Wih + (size_t)(2 * NHH + j2) * NH);
    }

    // prologue: zero state, stage x(0)
    {
        float4 z = make_float4(0.f, 0.f, 0.f, 0.f);
        float4* h1 = (float4*)sh_h1;
        float4* h2 = (float4*)sh_h2;
        for (int p = 0; p < 4; p++) h1[tid + p * 256] = z;
        for (int p = 0; p < 2; p++) h2[tid + p * 256] = z;
        const float4* e4 = (const float4*)g_emb;
        u64* xq = (u64*)sh_x[0];
        for (int p = 0; p < 2; p++) {
            int idx = tid + p * 256;
            int bl = idx & 15, kc = idx >> 4;
            float4 v = __ldg(e4 + ((size_t)(g * BPG + bl) * NS + 0) * 32 + kc);
            xq[(2 * kc) * BPG + bl]     = pack2(v.x, v.y);
            xq[(2 * kc + 1) * BPG + bl] = pack2(v.z, v.w);
        }
    }

    const u64* h1q = (const u64*)sh_h1;
    const u64* h2q = (const u64*)sh_h2;

    for (int i = 0; i <= NS; i++) {
        // reload full states produced last interval
        if (i > 0) {
            const float4* src = (const float4*)(g_h1x + (size_t)(((i - 1) & 1) * NG + g) * (NH * BPG));
            float4* d = (float4*)sh_h1;
#pragma unroll
            for (int p = 0; p < 4; p++) d[tid + p * 256] = __ldcg(src + tid + p * 256);
        }
        if (i > 1) {
            const float4* src = (const float4*)(g_h2x + (size_t)((i & 1) * NG + g) * (NHH * BPG));
            float4* d = (float4*)sh_h2;
#pragma unroll
            for (int p = 0; p < 2; p++) d[tid + p * 256] = __ldcg(src + tid + p * 256);
        }
        // prefetch x(i+1)
        if (i + 1 <= NS - 1) {
            const float4* e4 = (const float4*)g_emb;
            u64* xq = (u64*)sh_x[(i + 1) & 1];
#pragma unroll
            for (int p = 0; p < 2; p++) {
                int idx = tid + p * 256;
                int bl = idx & 15, kc = idx >> 4;
                float4 v = __ldg(e4 + ((size_t)(g * BPG + bl) * NS + (i + 1)) * 32 + kc);
                xq[(2 * kc) * BPG + bl]     = pack2(v.x, v.y);
                xq[(2 * kc + 1) * BPG + bl] = pack2(v.z, v.w);
            }
        }
        __syncthreads();

        // ---- enc1(i): h1(i) = GRU(x(i), h1(i-1)) ----
        if (i < NS) {
            const u64* xq = (const u64*)sh_x[i & 1];
            u64 aR0 = 0, aR1 = 0, aZ0 = 0, aZ1 = 0, aNh0 = 0, aNh1 = 0, aNx0 = 0, aNx1 = 0;
#pragma unroll 4
            for (int kc = 0; kc < NH / 4; kc++)
                GSTEP(w1r_h, w1z_h, w1n_h, h1q, kc, aR0, aR1, aZ0, aZ1, aNh0, aNh1);
#pragma unroll 4
            for (int kc = 0; kc < ND / 4; kc++)
                GSTEP(w1r_x, w1z_x, w1n_x, xq, kc, aR0, aR1, aZ0, aZ1, aNx0, aNx1);
            float h0o = sh_h1[KP(j1, 2 * bp)];
            float h1o = sh_h1[KP(j1, 2 * bp + 1)];
            float r0 = sigf(hsum2(aR0) + b1r);
            float z0 = sigf(hsum2(aZ0) + b1z);
            float n0 = tanhf(hsum2(aNx0) + b1in + r0 * (hsum2(aNh0) + b1hn));
            float r1 = sigf(hsum2(aR1) + b1r);
            float z1 = sigf(hsum2(aZ1) + b1z);
            float n1 = tanhf(hsum2(aNx1) + b1in + r1 * (hsum2(aNh1) + b1hn));
            float* dst = g_h1x + (size_t)((i & 1) * NG + g) * (NH * BPG);
            dst[KP(j1, 2 * bp)]     = (1.f - z0) * n0 + z0 * h0o;
            dst[KP(j1, 2 * bp + 1)] = (1.f - z1) * n1 + z1 * h1o;
        }

        // ---- enc2(i-1): h2(i-1) = GRU(h1(i-1), h2(i-2)) ----
        if (i >= 1 && tid < 128) {
            u64 aR0 = 0, aR1 = 0, aZ0 = 0, aZ1 = 0, aNh0 = 0, aNh1 = 0, aNx0 = 0, aNx1 = 0;
#pragma unroll 4
            for (int kc = 0; kc < NHH / 4; kc++)
                GSTEP(w2r_h, w2z_h, w2n_h, h2q, kc, aR0, aR1, aZ0, aZ1, aNh0, aNh1);
#pragma unroll 4
            for (int kc = 0; kc < NH / 4; kc++)
                GSTEP(w2r_x, w2z_x, w2n_x, h1q, kc, aR0, aR1, aZ0, aZ1, aNx0, aNx1);
            float h0o = sh_h2[KP(j2, 2 * bp)];
            float h1o = sh_h2[KP(j2, 2 * bp + 1)];
            float r0 = sigf(hsum2(aR0) + b2r);
            float z0 = sigf(hsum2(aZ0) + b2z);
            float n0 = tanhf(hsum2(aNx0) + b2in + r0 * (hsum2(aNh0) + b2hn));
            float r1 = sigf(hsum2(aR1) + b2r);
            float z1 = sigf(hsum2(aZ1) + b2z);
            float n1 = tanhf(hsum2(aNx1) + b2in + r1 * (hsum2(aNh1) + b2hn));
            float* dst = g_h2x + (size_t)(((i - 1) & 1) * NG + g) * (NHH * BPG);
            dst[KP(j2, 2 * bp)]     = (1.f - z0) * n0 + z0 * h0o;
            dst[KP(j2, 2 * bp + 1)] = (1.f - z1) * n1 + z1 * h1o;
        }

        if (i < NS) cbar();
    }
}

// ---------------- latent = h2(NS-1) @ l1_W^T + l1_b  (h2 final at par 1) ----------------
__global__ __launch_bounds__(256) void latent_kernel(const float* __restrict__ W,
                                                     const float* __restrict__ bias,
                                                     float* __restrict__ dout) {
    int id = blockIdx.x * 256 + threadIdx.x;   // 16384
    int l = id >> 8;
    int b = id & 255;
    int g = b >> 4, bb = b & 15;
    const u64* h = (const u64*)(g_h2x + (size_t)(NG + g) * (NHH * BPG));
    const ulonglong2* w = (const ulonglong2*)(W + (size_t)l * NHH);
    u64 a0 = 0, a1 = 0;
#pragma unroll 8
    for (int kc = 0; kc < NHH / 4; kc++) {
        ulonglong2 wv = w[kc];
        fma2(a0, wv.x, h[(2 * kc) * BPG + bb]);
        fma2(a1, wv.y, h[(2 * kc + 1) * BPG + bb]);
    }
    float acc = hsum2(a0) + hsum2(a1) + bias[l];
    g_lat[b * NL + l] = acc;
    dout[b * NL + l] = acc;
}

// ---------------- decoder constant gi1 ----------------
__global__ __launch_bounds__(256) void gi1_kernel(const float* __restrict__ Wih,
                                                  const float* __restrict__ bih) {
    int id = blockIdx.x * 256 + threadIdx.x;   // 98304
    int b = id / (3 * NHH);
    int r = id % (3 * NHH);
    const float* w = Wih + (size_t)r * NL;
    const float* v = g_lat + (size_t)b * NL;
    float acc = bih[r];
#pragma unroll
    for (int k = 0; k < NL; k++) acc += w[k] * v[k];
    g_gi1[id] = acc;
}

// ======================= DECODER (1 cluster barrier per step) =======================
__global__ __launch_bounds__(256, 1) __cluster_dims__(CLU, 1, 1)
void dec_kernel(const float* __restrict__ d1_Whh, const float* __restrict__ d1_bhh,
                const float* __restrict__ d2_Wih, const float* __restrict__ d2_Whh,
                const float* __restrict__ d2_bih, const float* __restrict__ d2_bhh) {
    __shared__ float sh_hd1[NHH * BPG];   // 8 KB
    __shared__ float sh_hd2[NH * BPG];    // 16 KB

    const int tid = threadIdx.x;
    const int rank = blockIdx.x & (CLU - 1);
    const int g = blockIdx.x >> 3;
    const int bp = tid & 7;

    // dec1 mapping: 16 j per CTA (tid < 128)
    const int jA = rank * 16 + (tid >> 3);
    float gir0 = 0, giz0 = 0, gin0 = 0, gir1 = 0, giz1 = 0, gin1 = 0;
    float bd1r = 0, bd1z = 0, bd1hn = 0;
    const ulonglong2 *wAr = 0, *wAz = 0, *wAn = 0;
    if (tid < 128) {
        int b0 = g * BPG + 2 * bp, b1 = b0 + 1;
        gir0 = g_gi1[(size_t)b0 * 3 * NHH + jA];
        giz0 = g_gi1[(size_t)b0 * 3 * NHH + NHH + jA];
        gin0 = g_gi1[(size_t)b0 * 3 * NHH + 2 * NHH + jA];
        gir1 = g_gi1[(size_t)b1 * 3 * NHH + jA];
        giz1 = g_gi1[(size_t)b1 * 3 * NHH + NHH + jA];
        gin1 = g_gi1[(size_t)b1 * 3 * NHH + 2 * NHH + jA];
        bd1r = d1_bhh[jA];
        bd1z = d1_bhh[NHH + jA];
        bd1hn = d1_bhh[2 * NHH + jA];
        wAr = (const ulonglong2*)(d1_Whh + (size_t)jA * NHH);
        wAz = (const ulonglong2*)(d1_Whh + (size_t)(NHH + jA) * NHH);
        wAn = (const ulonglong2*)(d1_Whh + (size_t)(2 * NHH + jA) * NHH);
    }

    // dec2 mapping: 32 j per CTA
    const int jB = rank * 32 + (tid >> 3);
    const float b2r  = d2_bih[jB] + d2_bhh[jB];
    const float b2z  = d2_bih[NH + jB] + d2_bhh[NH + jB];
    const float b2in = d2_bih[2 * NH + jB];
    const float b2hn = d2_bhh[2 * NH + jB];
    const ulonglong2* wBr_h = (const ulonglong2*)(d2_Whh + (size_t)jB * NH);
    const ulonglong2* wBz_h = (const ulonglong2*)(d2_Whh + (size_t)(NH + jB) * NH);
    const ulonglong2* wBn_h = (const ulonglong2*)(d2_Whh + (size_t)(2 * NH + jB) * NH);
    const ulonglong2* wBr_x = (const ulonglong2*)(d2_Wih + (size_t)jB * NHH);
    const ulonglong2* wBz_x = (const ulonglong2*)(d2_Wih + (size_t)(NH + jB) * NHH);
    const ulonglong2* wBn_x = (const ulonglong2*)(d2_Wih + (size_t)(2 * NH + jB) * NHH);

    {   // zero initial state
        float4 z = make_float4(0.f, 0.f, 0.f, 0.f);
        float4* h1 = (float4*)sh_hd1;
        float4* h2 = (float4*)sh_hd2;
        for (int p = 0; p < 2; p++) h1[tid + p * 256] = z;
        for (int p = 0; p < 4; p++) h2[tid + p * 256] = z;
    }

    const u64* hd1q = (const u64*)sh_hd1;
    const u64* hd2q = (const u64*)sh_hd2;

    for (int i = 0; i <= NS; i++) {
        if (i > 0) {
            const float4* src = (const float4*)(g_hd1x + (size_t)(((i - 1) & 1) * NG + g) * (NHH * BPG));
            float4* d = (float4*)sh_hd1;
#pragma unroll
            for (int p = 0; p < 2; p++) d[tid + p * 256] = __ldcg(src + tid + p * 256);
        }
        if (i > 1) {
            const float4* src = (const float4*)(g_hd2x + (size_t)((i & 1) * NG + g) * (NH * BPG));
            float4* d = (float4*)sh_hd2;
#pragma unroll
            for (int p = 0; p < 4; p++) d[tid + p * 256] = __ldcg(src + tid + p * 256);
        }
        __syncthreads();

        // ---- dec1(i): hd1(i) = GRU(gi1, hd1(i-1)) ----
        if (i < NS && tid < 128) {
            u64 aR0 = 0, aR1 = 0, aZ0 = 0, aZ1 = 0, aN0 = 0, aN1 = 0;
#pragma unroll 4
            for (int kc = 0; kc < NHH / 4; kc++)
                GSTEP(wAr, wAz, wAn, hd1q, kc, aR0, aR1, aZ0, aZ1, aN0, aN1);
            float h0o = sh_hd1[KP(jA, 2 * bp)];
            float h1o = sh_hd1[KP(jA, 2 * bp + 1)];
            float r0 = sigf(hsum2(aR0) + bd1r + gir0);
            float z0 = sigf(hsum2(aZ0) + bd1z + giz0);
            float n0 = tanhf(gin0 + r0 * (hsum2(aN0) + bd1hn));
            float r1 = sigf(hsum2(aR1) + bd1r + gir1);
            float z1 = sigf(hsum2(aZ1) + bd1z + giz1);
            float n1 = tanhf(gin1 + r1 * (hsum2(aN1) + bd1hn));
            float* dst = g_hd1x + (size_t)((i & 1) * NG + g) * (NHH * BPG);
            dst[KP(jA, 2 * bp)]     = (1.f - z0) * n0 + z0 * h0o;
            dst[KP(jA, 2 * bp + 1)] = (1.f - z1) * n1 + z1 * h1o;
        }

        // ---- dec2(i-1): hd2(i-1) = GRU(hd1(i-1), hd2(i-2)) ----
        if (i >= 1) {
            u64 aR0 = 0, aR1 = 0, aZ0 = 0, aZ1 = 0, aNh0 = 0, aNh1 = 0, aNx0 = 0, aNx1 = 0;
#pragma unroll 4
            for (int kc = 0; kc < NH / 4; kc++)
                GSTEP(wBr_h, wBz_h, wBn_h, hd2q, kc, aR0, aR1, aZ0, aZ1, aNh0, aNh1);
#pragma unroll 4
            for (int kc = 0; kc < NHH / 4; kc++)
                GSTEP(wBr_x, wBz_x, wBn_x, hd1q, kc, aR0, aR1, aZ0, aZ1, aNx0, aNx1);
            float h0o = sh_hd2[KP(jB, 2 * bp)];
            float h1o = sh_hd2[KP(jB, 2 * bp + 1)];
            float r0 = sigf(hsum2(aR0) + b2r);
            float z0 = sigf(hsum2(aZ0) + b2z);
            float n0 = tanhf(hsum2(aNx0) + b2in + r0 * (hsum2(aNh0) + b2hn));
            float r1 = sigf(hsum2(aR1) + b2r);
            float z1 = sigf(hsum2(aZ1) + b2z);
            float n1 = tanhf(hsum2(aNx1) + b2in + r1 * (hsum2(aNh1) + b2hn));
            float hn0 = (1.f - z0) * n0 + z0 * h0o;
            float hn1 = (1.f - z1) * n1 + z1 * h1o;
            float* dst = g_hd2x + (size_t)(((i - 1) & 1) * NG + g) * (NH * BPG);
            dst[KP(jB, 2 * bp)]     = hn0;
            dst[KP(jB, 2 * bp + 1)] = hn1;
            *(float2*)(g_h2seq + ((size_t)((i - 1) * NG + g) * NH + jB) * BPG + 2 * bp) =
                make_float2(hn0, hn1);
        }

        if (i < NS) cbar();
    }
}

// ---------------- l2 projection + MSE loss: CTA = (t, g) ----------------
__global__ __launch_bounds__(256) void l2loss_kernel(const float* __restrict__ W,
                                                     const float* __restrict__ bias) {
    __shared__ float shW[64 * 128];   // [k][d] 32 KB
    __shared__ float shH[64 * BPG];   // [k][b] 4 KB
    __shared__ double sred[8];
    const int t = blockIdx.x >> 4;
    const int g = blockIdx.x & 15;
    const int tid = threadIdx.x;
    const int d = tid & 127;
    const int half = tid >> 7;

    float acc[8];
#pragma unroll
    for (int i = 0; i < 8; i++) acc[i] = bias[d];

    const float4* W4 = (const float4*)W;
    const float4* H4 = (const float4*)g_h2seq;

    for (int kt = 0; kt < 4; kt++) {
        for (int p = 0; p < 8; p++) {
            int idx = tid + p * 256;
            int dd = idx >> 4, kc = idx & 15;
            float4 v = __ldg(W4 + (size_t)dd * 64 + kt * 16 + kc);
            shW[(kc * 4 + 0) * 128 + dd] = v.x;
            shW[(kc * 4 + 1) * 128 + dd] = v.y;
            shW[(kc * 4 + 2) * 128 + dd] = v.z;
            shW[(kc * 4 + 3) * 128 + dd] = v.w;
        }
        ((float4*)shH)[tid] = __ldg(H4 + ((size_t)(t * NG + g) * NH + kt * 64) * 4 + tid);
        __syncthreads();
#pragma unroll 4
        for (int k = 0; k < 64; k++) {
            float w = shW[k * 128 + d];
            float4 hA = *(const float4*)&shH[k * BPG + half * 8];
            float4 hB = *(const float4*)&shH[k * BPG + half * 8 + 4];
            acc[0] += w * hA.x; acc[1] += w * hA.y; acc[2] += w * hA.z; acc[3] += w * hA.w;
            acc[4] += w * hB.x; acc[5] += w * hB.y; acc[6] += w * hB.z; acc[7] += w * hB.w;
        }
        __syncthreads();
    }

    float se = 0.f;
#pragma unroll
    for (int i = 0; i < 8; i++) {
        int b = g * BPG + half * 8 + i;
        float e = g_emb[((size_t)b * NS + t) * ND + d];
        float diff = acc[i] - e;
        se += diff * diff;
    }
    for (int o = 16; o > 0; o >>= 1) se += __shfl_down_sync(0xffffffffu, se, o);
    if ((tid & 31) == 0) sred[tid >> 5] = (double)se;
    __syncthreads();
    if (tid == 0) {
        double s = 0;
        for (int i = 0; i < 8; i++) s += sred[i];
        atomicAdd(&g_losspart[blockIdx.x & 1023], s);
    }
}

// ---------------- finalize ----------------
__global__ void final_kernel(float* __restrict__ dout) {
    __shared__ double s[256];
    int tid = threadIdx.x;
    double v = g_losspart[tid] + g_losspart[tid + 256] + g_losspart[tid + 512] + g_losspart[tid + 768];
    s[tid] = v;
    __syncthreads();
    for (int o = 128; o > 0; o >>= 1) {
        if (tid < o) s[tid] += s[tid + o];
        __syncthreads();
    }
    if (tid == 0) dout[NB * NL] = (float)(s[0] / (double)((size_t)NB * NS * ND));
}

// ---------------- launch ----------------
extern "C" void kernel_launch(void* const* d_in, const int* in_sizes, int n_in,
                              void* d_out, int out_size) {
    const int*   tok     = (const int*)d_in[0];
    const float* path_w  = (const float*)d_in[1];
    const float* sys_w   = (const float*)d_in[2];
    const float* e1_Wih  = (const float*)d_in[3];
    const float* e1_Whh  = (const float*)d_in[4];
    const float* e1_bih  = (const float*)d_in[5];
    const float* e1_bhh  = (const float*)d_in[6];
    const float* e2_Wih  = (const float*)d_in[7];
    const float* e2_Whh  = (const float*)d_in[8];
    const float* e2_bih  = (const float*)d_in[9];
    const float* e2_bhh  = (const float*)d_in[10];
    const float* l1_W    = (const float*)d_in[11];
    const float* l1_b    = (const float*)d_in[12];
    const float* d1_Wih  = (const float*)d_in[13];
    const float* d1_Whh  = (const float*)d_in[14];
    const float* d1_bih  = (const float*)d_in[15];
    const float* d1_bhh  = (const float*)d_in[16];
    const float* d2_Wih  = (const float*)d_in[17];
    const float* d2_Whh  = (const float*)d_in[18];
    const float* d2_bih  = (const float*)d_in[19];
    const float* d2_bhh  = (const float*)d_in[20];
    const float* l2_W    = (const float*)d_in[21];
    const float* l2_b    = (const float*)d_in[22];
    float* dout = (float*)d_out;

    init_kernel<<<4, 256>>>();
    emb_kernel<<<4096, 256>>>(tok, path_w, sys_w);
    enc_kernel<<<NG * CLU, 256>>>(e1_Wih, e1_Whh, e1_bih, e1_bhh,
                                  e2_Wih, e2_Whh, e2_bih, e2_bhh);
    latent_kernel<<<64, 256>>>(l1_W, l1_b, dout);
    gi1_kernel<<<384, 256>>>(d1_Wih, d1_bih);
    dec_kernel<<<NG * CLU, 256>>>(d1_Whh, d1_bhh, d2_Wih, d2_Whh, d2_bih, d2_bhh);
    l2loss_kernel<<<NS * NG, 256>>>(l2_W, l2_b);
    final_kernel<<<1, 256>>>(dout);
}